// round 17
// baseline (speedup 1.0000x reference)
#include <cuda_runtime.h>
#include <cuda_fp16.h>

#define BB 8
#define SS 16
#define TT 128
#define DD 64
#define NN 2048
#define P0  (0.00048828125f)   // 1/2048
#define C2E (0.18033688011112042f)   // 0.125 * log2(e)

typedef unsigned long long ull;
typedef unsigned int uint;

// fp16 split operands
__device__ __half g_qh[BB*NN*DD], g_ql[BB*NN*DD];
__device__ __half g_kh[BB*NN*DD], g_kl[BB*NN*DD];
__device__ __half g_vph[BB*NN*DD];            // [b][m][d] single fp16, m = t*16+s

#define QOFF(r,c) ((uint)((r)*128 + (((c) ^ ((r)&7)) << 4)))
#define VOFF(r,c) ((uint)((r)*256 + (((c) ^ ((r)&7)) << 4)))

__device__ __forceinline__ uint smem_u32(const void* p){
    uint a; asm("{ .reg .u64 t; cvta.to.shared.u64 t, %1; cvt.u32.u64 %0, t; }" : "=r"(a) : "l"(p));
    return a;
}
__device__ __forceinline__ void cpa16(uint dst, const void* src){
    asm volatile("cp.async.cg.shared.global [%0], [%1], 16;"
        :: "r"(dst), "l"(__cvta_generic_to_global(src)) : "memory");
}
#define CPA_COMMIT() asm volatile("cp.async.commit_group;" ::: "memory")
#define CPA_WAIT0()  asm volatile("cp.async.wait_group 0;" ::: "memory")

__device__ __forceinline__ uint4 ldsm4(uint addr){
    uint4 r;
    asm volatile("ldmatrix.sync.aligned.m8n8.x4.shared.b16 {%0,%1,%2,%3}, [%4];"
        : "=r"(r.x), "=r"(r.y), "=r"(r.z), "=r"(r.w) : "r"(addr));
    return r;
}
__device__ __forceinline__ uint4 ldsm4t(uint addr){
    uint4 r;
    asm volatile("ldmatrix.sync.aligned.m8n8.x4.trans.shared.b16 {%0,%1,%2,%3}, [%4];"
        : "=r"(r.x), "=r"(r.y), "=r"(r.z), "=r"(r.w) : "r"(addr));
    return r;
}
__device__ __forceinline__ void mma16816(float* d, uint4 a, uint b0, uint b1){
    asm volatile("mma.sync.aligned.m16n8k16.row.col.f32.f16.f16.f32 "
        "{%0,%1,%2,%3}, {%4,%5,%6,%7}, {%8,%9}, {%0,%1,%2,%3};"
        : "+f"(d[0]), "+f"(d[1]), "+f"(d[2]), "+f"(d[3])
        : "r"(a.x), "r"(a.y), "r"(a.z), "r"(a.w), "r"(b0), "r"(b1));
}
__device__ __forceinline__ float ex2f(float x){
    float r; asm("ex2.approx.f32 %0, %1;" : "=f"(r) : "f"(x)); return r;
}
__device__ __forceinline__ uint ex2h2(uint x){
    uint r; asm("ex2.approx.f16x2 %0, %1;" : "=r"(r) : "r"(x)); return r;
}

// ---------------- kernel 1: QKV projection via mma.sync ----------------
#define QK_XH 0
#define QK_XL 16384
#define QK_WH 32768
#define QK_WL 57344
#define QK_BS 81920
#define SMEM_QKV 82944

__global__ void __launch_bounds__(512)
qkv_kernel(const float* __restrict__ x,
           const float* __restrict__ Wq_w, const float* __restrict__ Wq_b,
           const float* __restrict__ Wk_w, const float* __restrict__ Wk_b,
           const float* __restrict__ Wv_w, const float* __restrict__ Wv_b)
{
    extern __shared__ char smq[];
    uint sb = smem_u32(smq);
    float* bs = (float*)(smq + QK_BS);
    int tid = threadIdx.x;
    int gr0 = blockIdx.x * 128;
    int b_  = blockIdx.x >> 4;
    int s_  = blockIdx.x & 15;

    #pragma unroll
    for (int it = 0; it < 2; it++) {
        int idx = tid + (it << 9);
        int r = idx >> 3, c = idx & 7;
        const float* src = x + (size_t)(gr0 + r)*64 + c*8;
        float4 v0 = *(const float4*)src;
        float4 v1 = *(const float4*)(src + 4);
        float f[8] = {v0.x,v0.y,v0.z,v0.w,v1.x,v1.y,v1.z,v1.w};
        __half h[8], lo[8];
        #pragma unroll
        for (int i = 0; i < 8; i++) {
            h[i]  = __float2half_rn(f[i]);
            lo[i] = __float2half_rn(f[i] - __half2float(h[i]));
        }
        *(uint4*)(smq + QK_XH + QOFF(r, c)) = *(uint4*)h;
        *(uint4*)(smq + QK_XL + QOFF(r, c)) = *(uint4*)lo;
    }
    #pragma unroll
    for (int it = 0; it < 3; it++) {
        int idx = tid + it*512;
        int n = idx >> 3, c = idx & 7;
        const float* wsrc = (n < 64) ? Wq_w : ((n < 128) ? Wk_w : Wv_w);
        const float* src = wsrc + (size_t)(n & 63)*64 + c*8;
        float4 v0 = *(const float4*)src;
        float4 v1 = *(const float4*)(src + 4);
        float f[8] = {v0.x,v0.y,v0.z,v0.w,v1.x,v1.y,v1.z,v1.w};
        __half h[8], lo[8];
        #pragma unroll
        for (int i = 0; i < 8; i++) {
            h[i]  = __float2half_rn(f[i]);
            lo[i] = __float2half_rn(f[i] - __half2float(h[i]));
        }
        *(uint4*)(smq + QK_WH + QOFF(n, c)) = *(uint4*)h;
        *(uint4*)(smq + QK_WL + QOFF(n, c)) = *(uint4*)lo;
    }
    if (tid < 192)
        bs[tid] = (tid < 64) ? Wq_b[tid] : ((tid < 128) ? Wk_b[tid-64] : Wv_b[tid-128]);
    __syncthreads();

    int wid  = tid >> 5, lane = tid & 31;
    int wr   = wid >> 1;
    int wh   = wid & 1;
    int m0   = wr << 4;
    int nb   = wh * 96;
    int lq   = lane & 3;
    int lr   = lane >> 2;
    int rA   = m0 + lr, rB = rA + 8;
    int aRow = m0 + (lane & 7) + ((lane >> 3) & 1)*8;
    int aChS = (lane >> 4);
    int bRowOff = (lane & 7) + ((lane >= 16) ? 8 : 0);
    int bChS = ((lane >> 3) & 1);

    float acc[12][4];
    #pragma unroll
    for (int f = 0; f < 12; f++) { acc[f][0]=0; acc[f][1]=0; acc[f][2]=0; acc[f][3]=0; }

    #pragma unroll
    for (int ks = 0; ks < 4; ks++) {
        uint4 Ah = ldsm4(sb + QK_XH + QOFF(aRow, 2*ks + aChS));
        uint4 Al = ldsm4(sb + QK_XL + QOFF(aRow, 2*ks + aChS));
        #pragma unroll
        for (int fp = 0; fp < 6; fp++) {
            int n = nb + 16*fp;
            uint4 Bh = ldsm4(sb + QK_WH + QOFF(n + bRowOff, 2*ks + bChS));
            mma16816(acc[2*fp],     Ah, Bh.x, Bh.y);
            mma16816(acc[2*fp + 1], Ah, Bh.z, Bh.w);
            mma16816(acc[2*fp],     Al, Bh.x, Bh.y);
            mma16816(acc[2*fp + 1], Al, Bh.z, Bh.w);
            uint4 Bl = ldsm4(sb + QK_WL + QOFF(n + bRowOff, 2*ks + bChS));
            mma16816(acc[2*fp],     Ah, Bl.x, Bl.y);
            mma16816(acc[2*fp + 1], Ah, Bl.z, Bl.w);
        }
    }

    #pragma unroll
    for (int f = 0; f < 12; f++) {
        int col0 = nb + 8*f + 2*lq;
        int mat  = col0 >> 6;
        int cc   = col0 & 63;
        float b0 = bs[col0], b1 = bs[col0 + 1];
        float vA0 = acc[f][0] + b0, vA1 = acc[f][1] + b1;
        float vB0 = acc[f][2] + b0, vB1 = acc[f][3] + b1;
        __half hA0 = __float2half_rn(vA0), hA1 = __float2half_rn(vA1);
        __half hB0 = __float2half_rn(vB0), hB1 = __float2half_rn(vB1);
        if (mat < 2) {
            __half* dh = mat ? g_kh : g_qh;
            __half* dl = mat ? g_kl : g_ql;
            __half2 hA(hA0, hA1), hB(hB0, hB1);
            __half2 lA(__float2half_rn(vA0 - __half2float(hA0)),
                       __float2half_rn(vA1 - __half2float(hA1)));
            __half2 lB(__float2half_rn(vB0 - __half2float(hB0)),
                       __float2half_rn(vB1 - __half2float(hB1)));
            *(uint*)(dh + (size_t)(gr0 + rA)*64 + cc) = *(uint*)&hA;
            *(uint*)(dh + (size_t)(gr0 + rB)*64 + cc) = *(uint*)&hB;
            *(uint*)(dl + (size_t)(gr0 + rA)*64 + cc) = *(uint*)&lA;
            *(uint*)(dl + (size_t)(gr0 + rB)*64 + cc) = *(uint*)&lB;
        } else {
            int mA = rA*16 + s_, mB = rB*16 + s_;
            __half2 hA(hA0, hA1), hB(hB0, hB1);
            *(uint*)(g_vph + ((size_t)(b_ << 11) + mA)*64 + cc) = *(uint*)&hA;
            *(uint*)(g_vph + ((size_t)(b_ << 11) + mB)*64 + cc) = *(uint*)&hB;
        }
    }
}

// ---------------- attention (512 threads, fp16, Q frags in registers) ----------------
#define OFF_QH 0
#define OFF_QL 16384
#define OFF_K0 32768
#define OFF_K0L 49152
#define OFF_K1 65536
#define OFF_K1L 81920
#define OFF_V0 98304
#define OFF_V1 114688
#define OFF_V2 131072
#define OFF_P0 147456
#define OFF_P1 180224
#define OFF_MSB  212992
#define OFF_STLP 215040
#define OFF_UF   216064
#define OFF_FLAG 216576
#define OFF_TAGS 216580
#define SMEM_AT  216704

__global__ void __launch_bounds__(512, 1)
attn_kernel(const int* __restrict__ tags, const float* __restrict__ mask,
            float* __restrict__ ctx, float* __restrict__ p)
{
    extern __shared__ char smem[];
    uint sb = smem_u32(smem);
    int tid  = threadIdx.x;
    int wid  = tid >> 5, lane = tid & 31;
    int wr   = wid >> 1;
    int wh   = wid & 1;
    int m0   = wr << 4;
    int nb   = wh << 6;
    int db   = wh << 5;
    int s    = blockIdx.x;
    int b    = blockIdx.y;
    int lq   = lane & 3;
    int lr   = lane >> 2;
    int rA   = m0 + lr, rB = rA + 8;

    int*   tgs  = (int*)(smem + OFF_TAGS);
    uint*  msb  = (uint*)(smem + OFF_MSB);
    float* stlp = (float*)(smem + OFF_STLP);
    int*   ufr  = (int*)(smem + OFF_UF);
    int*   flg  = (int*)(smem + OFF_FLAG);

    if (tid < 16) tgs[tid] = tags[b*16 + tid];
    if (tid == 0) flg[0] = 0;
    {
        int tt = tid >> 2, w = tid & 3;
        uint bits = 0;
        #pragma unroll 8
        for (int j = 0; j < 32; j++)
            bits |= (mask[(size_t)tt*128 + w*32 + j] != 0.f ? 1u : 0u) << j;
        msb[tid] = bits;
    }
    // stage Q hi+lo synchronously (ready before loops; cp.async groups = K/V only)
    #pragma unroll
    for (int it = 0; it < 2; it++) {
        int idx = tid + (it << 9);
        int r = idx >> 3, c = idx & 7;
        size_t se = ((size_t)((b << 11) + (s << 7) + r))*64 + c*8;
        *(uint4*)(smem + OFF_QH + QOFF(r, c)) = *(const uint4*)(g_qh + se);
        *(uint4*)(smem + OFF_QL + QOFF(r, c)) = *(const uint4*)(g_ql + se);
    }
    __syncthreads();

    int mytag = tgs[s];
    uint vmask = 0;
    #pragma unroll
    for (int s2 = 0; s2 < 16; s2++) if (tgs[s2] == mytag) vmask |= 1u << s2;
    int vlist[16], nv = 0;
    #pragma unroll
    for (int s2 = 0; s2 < 16; s2++) if ((vmask >> s2) & 1) vlist[nv++] = s2;

    uint mbA = 0, mbB = 0;
    #pragma unroll
    for (int f = 0; f < 8; f++)
        #pragma unroll
        for (int u = 0; u < 2; u++) {
            int cw = nb + 8*f + 2*lq + u;
            mbA |= ((msb[rA*4 + (cw >> 5)] >> (cw & 31)) & 1u) << (f*2 + u);
            mbB |= ((msb[rB*4 + (cw >> 5)] >> (cw & 31)) & 1u) << (f*2 + u);
        }
    int fullm = (mbA == 0xffffu) && (mbB == 0xffffu);

    int aRow = m0 + (lane & 7) + ((lane >> 3) & 1)*8;
    int aChS = (lane >> 4);
    int bRowOff = (lane & 7) + ((lane >= 16) ? 8 : 0);
    int bChS = ((lane >> 3) & 1);
    int vRowOff = (lane & 7) + (((lane >> 3) & 1) << 3);
    int vChS = (lane >> 4);

    // hoist Q fragments into registers (loop-invariant across all blocks)
    uint4 QAh[4], QAl[4];
    #pragma unroll
    for (int ks = 0; ks < 4; ks++) {
        QAh[ks] = ldsm4(sb + OFF_QH + QOFF(aRow, 2*ks + aChS));
        QAl[ks] = ldsm4(sb + OFF_QL + QOFF(aRow, 2*ks + aChS));
    }

    const __half* gb_kh = g_kh + ((size_t)b << 17);
    const __half* gb_kl = g_kl + ((size_t)b << 17);
    const __half* gb_vh = g_vph + ((size_t)b << 17);

    // ================ pass 1: l = sum exp(s), hi-only QK ================
    float lsA = 0.f, lsB = 0.f;
    {
        #pragma unroll
        for (int it = 0; it < 2; it++) {
            int idx = tid + (it << 9);
            int r = idx >> 3, c = idx & 7;
            cpa16(sb + OFF_K0 + QOFF(r, c), gb_kh + ((size_t)((vlist[0] << 7) + r))*64 + c*8);
        }
        CPA_COMMIT();
        for (int vi = 0; vi < nv; vi++) {
            CPA_WAIT0();
            __syncthreads();
            if (vi + 1 < nv) {
                uint dsto = ((vi + 1) & 1) ? OFF_K1 : OFF_K0;
                #pragma unroll
                for (int it = 0; it < 2; it++) {
                    int idx = tid + (it << 9);
                    int r = idx >> 3, c = idx & 7;
                    cpa16(sb + dsto + QOFF(r, c), gb_kh + ((size_t)((vlist[vi+1] << 7) + r))*64 + c*8);
                }
                CPA_COMMIT();
            }
            uint kb = sb + ((vi & 1) ? OFF_K1 : OFF_K0);
            float acc[8][4];
            #pragma unroll
            for (int f = 0; f < 8; f++) { acc[f][0]=0; acc[f][1]=0; acc[f][2]=0; acc[f][3]=0; }
            #pragma unroll
            for (int ks = 0; ks < 4; ks++) {
                #pragma unroll
                for (int fp = 0; fp < 4; fp++) {
                    int n = nb + 16*fp;
                    uint4 Bv = ldsm4(kb + QOFF(n + bRowOff, 2*ks + bChS));
                    mma16816(acc[2*fp],     QAh[ks], Bv.x, Bv.y);
                    mma16816(acc[2*fp + 1], QAh[ks], Bv.z, Bv.w);
                }
            }
            if (fullm) {
                __half2 hsA = __floats2half2_rn(0.f, 0.f);
                __half2 hsB = hsA;
                #pragma unroll
                for (int f = 0; f < 8; f++) {
                    __half2 aA = __floats2half2_rn(acc[f][0]*C2E, acc[f][1]*C2E);
                    __half2 aB = __floats2half2_rn(acc[f][2]*C2E, acc[f][3]*C2E);
                    uint eA = ex2h2(*(uint*)&aA);
                    uint eB = ex2h2(*(uint*)&aB);
                    hsA = __hadd2(hsA, *(__half2*)&eA);
                    hsB = __hadd2(hsB, *(__half2*)&eB);
                }
                float2 fA = __half22float2(hsA), fB = __half22float2(hsB);
                lsA += fA.x + fA.y;
                lsB += fB.x + fB.y;
            } else {
                #pragma unroll
                for (int f = 0; f < 8; f++) {
                    lsA += (((mbA >> (2*f)) & 1)   ? ex2f(acc[f][0]*C2E) : 0.f)
                         + (((mbA >> (2*f+1)) & 1) ? ex2f(acc[f][1]*C2E) : 0.f);
                    lsB += (((mbB >> (2*f)) & 1)   ? ex2f(acc[f][2]*C2E) : 0.f)
                         + (((mbB >> (2*f+1)) & 1) ? ex2f(acc[f][3]*C2E) : 0.f);
                }
            }
        }
    }
    // prefetch pass-2 block 0 (K hi+lo, V) while reducing
    #pragma unroll
    for (int it = 0; it < 2; it++) {
        int idx = tid + (it << 9);
        int r = idx >> 3, c = idx & 7;
        size_t se = ((size_t)((vlist[0] << 7) + r))*64 + c*8;
        cpa16(sb + OFF_K0  + QOFF(r, c), gb_kh + se);
        cpa16(sb + OFF_K0L + QOFF(r, c), gb_kl + se);
        cpa16(sb + OFF_V0  + QOFF(r, c), gb_vh + se);
    }
    CPA_COMMIT();

    lsA += __shfl_xor_sync(0xffffffffu, lsA, 1);
    lsA += __shfl_xor_sync(0xffffffffu, lsA, 2);
    lsB += __shfl_xor_sync(0xffffffffu, lsB, 1);
    lsB += __shfl_xor_sync(0xffffffffu, lsB, 2);
    __syncthreads();
    if (lq == 0) { stlp[rA*2 + wh] = lsA; stlp[rB*2 + wh] = lsB; }
    __syncthreads();
    float lA = stlp[rA*2] + stlp[rA*2+1];
    float lB = stlp[rB*2] + stlp[rB*2+1];
    int ufA = (lA == 0.f), ufB = (lB == 0.f);
    float invlA = ufA ? 0.f : 1.f/lA;
    float invlB = ufB ? 0.f : 1.f/lB;
    if (lq == 0 && wh == 0) { ufr[rA] = ufA; ufr[rB] = ufB; if (ufA | ufB) flg[0] = 1; }
    __syncthreads();
    int anyU = flg[0];
    if (anyU) {
        #pragma unroll
        for (int it = 0; it < 2; it++) {
            int idx = tid + (it << 9);
            int r = idx >> 3, c = idx & 7;
            size_t se = ((size_t)r)*64 + c*8;
            cpa16(sb + OFF_K0  + QOFF(r, c), gb_kh + se);
            cpa16(sb + OFF_K0L + QOFF(r, c), gb_kl + se);
            cpa16(sb + OFF_V0  + QOFF(r, c), gb_vh + se);
        }
        CPA_COMMIT();
    }

    // ================ pass 2: single sync per block, deferred AV ================
    int nproc = anyU ? 16 : nv;
    float accAV[4][4];
    #pragma unroll
    for (int f = 0; f < 4; f++) { accAV[f][0]=0; accAV[f][1]=0; accAV[f][2]=0; accAV[f][3]=0; }
    float* pbase = p + ((size_t)(b*2048 + s*128))*2048;
    const uint voffs0 = OFF_V0, voffs1 = OFF_V1, voffs2 = OFF_V2;

    for (int i = 0; i < nproc; i++) {
        int s2 = anyU ? i : vlist[i];
        int bv = (vmask >> s2) & 1;
        CPA_WAIT0();
        __syncthreads();   // K(i),V(i) ready; P(i-1) visible
        // deferred AV on block i-1
        if (i > 0) {
            uint pb2 = sb + (((i-1) & 1) ? OFF_P1 : OFF_P0);
            int vm3 = (i-1) % 3;
            uint vb2 = sb + (vm3 == 0 ? voffs0 : (vm3 == 1 ? voffs1 : voffs2));
            #pragma unroll
            for (int ks = 0; ks < 8; ks++) {
                uint4 Ah = ldsm4(pb2 + VOFF(aRow, 2*ks + aChS));
                #pragma unroll
                for (int fp = 0; fp < 2; fp++) {
                    int cch = ((db + 16*fp) >> 3) + vChS;
                    uint4 Bh = ldsm4t(vb2 + QOFF(16*ks + vRowOff, cch));
                    mma16816(accAV[2*fp],     Ah, Bh.x, Bh.y);
                    mma16816(accAV[2*fp + 1], Ah, Bh.z, Bh.w);
                }
            }
        }
        // prefetch block i+1
        if (i + 1 < nproc) {
            int s3 = anyU ? (i + 1) : vlist[i + 1];
            uint dh = ((i + 1) & 1) ? OFF_K1 : OFF_K0;
            uint dl = ((i + 1) & 1) ? OFF_K1L : OFF_K0L;
            int vn3 = (i + 1) % 3;
            uint dv = (vn3 == 0 ? voffs0 : (vn3 == 1 ? voffs1 : voffs2));
            #pragma unroll
            for (int it = 0; it < 2; it++) {
                int idx = tid + (it << 9);
                int r = idx >> 3, c = idx & 7;
                size_t se = ((size_t)((s3 << 7) + r))*64 + c*8;
                cpa16(sb + dh + QOFF(r, c), gb_kh + se);
                cpa16(sb + dl + QOFF(r, c), gb_kl + se);
                cpa16(sb + dv + QOFF(r, c), gb_vh + se);
            }
            CPA_COMMIT();
        }
        uint kbh = sb + ((i & 1) ? OFF_K1 : OFF_K0);
        uint kbl = sb + ((i & 1) ? OFF_K1L : OFF_K0L);
        uint pcur = sb + ((i & 1) ? OFF_P1 : OFF_P0);
        if (bv) {
            float acc[8][4];
            #pragma unroll
            for (int f = 0; f < 8; f++) { acc[f][0]=0; acc[f][1]=0; acc[f][2]=0; acc[f][3]=0; }
            #pragma unroll
            for (int ks = 0; ks < 4; ks++) {
                #pragma unroll
                for (int fp = 0; fp < 4; fp++) {
                    int n = nb + 16*fp;
                    uint4 Bh = ldsm4(kbh + QOFF(n + bRowOff, 2*ks + bChS));
                    mma16816(acc[2*fp],     QAh[ks], Bh.x, Bh.y);
                    mma16816(acc[2*fp + 1], QAh[ks], Bh.z, Bh.w);
                    mma16816(acc[2*fp],     QAl[ks], Bh.x, Bh.y);
                    mma16816(acc[2*fp + 1], QAl[ks], Bh.z, Bh.w);
                    uint4 Bl = ldsm4(kbl + QOFF(n + bRowOff, 2*ks + bChS));
                    mma16816(acc[2*fp],     QAh[ks], Bl.x, Bl.y);
                    mma16816(acc[2*fp + 1], QAh[ks], Bl.z, Bl.w);
                }
            }
            #pragma unroll
            for (int f = 0; f < 8; f++) {
                float e0, e1, e2, e3;
                if (fullm) {
                    e0 = ex2f(acc[f][0]*C2E);
                    e1 = ex2f(acc[f][1]*C2E);
                    e2 = ex2f(acc[f][2]*C2E);
                    e3 = ex2f(acc[f][3]*C2E);
                } else {
                    e0 = ((mbA >> (2*f)) & 1)   ? ex2f(acc[f][0]*C2E) : 0.f;
                    e1 = ((mbA >> (2*f+1)) & 1) ? ex2f(acc[f][1]*C2E) : 0.f;
                    e2 = ((mbB >> (2*f)) & 1)   ? ex2f(acc[f][2]*C2E) : 0.f;
                    e3 = ((mbB >> (2*f+1)) & 1) ? ex2f(acc[f][3]*C2E) : 0.f;
                }
                float p0 = ufA ? P0 : e0*invlA;
                float p1 = ufA ? P0 : e1*invlA;
                float p2 = ufB ? P0 : e2*invlB;
                float p3 = ufB ? P0 : e3*invlB;
                int cw = nb + 8*f + 2*lq;
                __stcs((float2*)(pbase + (size_t)rA*2048 + s2*128 + cw), make_float2(p0, p1));
                __stcs((float2*)(pbase + (size_t)rB*2048 + s2*128 + cw), make_float2(p2, p3));
                int ch = (wh << 3) + f;
                __half2 hA = __floats2half2_rn(p0, p1);
                __half2 hB = __floats2half2_rn(p2, p3);
                *(uint*)(smem + (pcur - sb) + VOFF(rA, ch) + 4*lq) = *(uint*)&hA;
                *(uint*)(smem + (pcur - sb) + VOFF(rB, ch) + 4*lq) = *(uint*)&hB;
            }
        } else {
            for (int i2 = tid; i2 < 2048; i2 += 512) {
                int r = i2 >> 4, c = i2 & 15;
                float pv = ufr[r] ? P0 : 0.f;
                __half2 hv2 = __floats2half2_rn(pv, pv);
                uint hw = *(uint*)&hv2;
                uint4 hv; hv.x = hv.y = hv.z = hv.w = hw;
                *(uint4*)(smem + (pcur - sb) + VOFF(r, c)) = hv;
            }
            for (int i2 = tid; i2 < 4096; i2 += 512) {
                int r = i2 >> 5, c4 = i2 & 31;
                float pv = ufr[r] ? P0 : 0.f;
                __stcs((float4*)(pbase + (size_t)r*2048 + s2*128 + (c4 << 2)),
                       make_float4(pv, pv, pv, pv));
            }
        }
    }
    // epilogue AV on last block
    __syncthreads();
    {
        int il = nproc - 1;
        uint pb2 = sb + ((il & 1) ? OFF_P1 : OFF_P0);
        int vm3 = il % 3;
        uint vb2 = sb + (vm3 == 0 ? voffs0 : (vm3 == 1 ? voffs1 : voffs2));
        #pragma unroll
        for (int ks = 0; ks < 8; ks++) {
            uint4 Ah = ldsm4(pb2 + VOFF(aRow, 2*ks + aChS));
            #pragma unroll
            for (int fp = 0; fp < 2; fp++) {
                int cch = ((db + 16*fp) >> 3) + vChS;
                uint4 Bh = ldsm4t(vb2 + QOFF(16*ks + vRowOff, cch));
                mma16816(accAV[2*fp],     Ah, Bh.x, Bh.y);
                mma16816(accAV[2*fp + 1], Ah, Bh.z, Bh.w);
            }
        }
    }

    if (!anyU) {
        for (int s2 = 0; s2 < 16; s2++) {
            if ((vmask >> s2) & 1) continue;
            float4 z = make_float4(0.f, 0.f, 0.f, 0.f);
            for (int i2 = tid; i2 < 4096; i2 += 512) {
                int r = i2 >> 5, c4 = i2 & 31;
                __stcs((float4*)(pbase + (size_t)r*2048 + s2*128 + (c4 << 2)), z);
            }
        }
    }

    {
        float* cb = ctx + ((size_t)(b*2048 + s*128))*64;
        #pragma unroll
        for (int f = 0; f < 2; f++) {
            int dc = db + 8*f + 2*lq;
            __stcs((float2*)(cb + (size_t)rA*64 + dc), make_float2(accAV[f][0], accAV[f][1]));
            __stcs((float2*)(cb + (size_t)rB*64 + dc), make_float2(accAV[f][2], accAV[f][3]));
        }
        #pragma unroll
        for (int f = 2; f < 4; f++) {
            int dc = db + 8*(f-2) + 16 + 2*lq;
            __stcs((float2*)(cb + (size_t)rA*64 + dc), make_float2(accAV[f][0], accAV[f][1]));
            __stcs((float2*)(cb + (size_t)rB*64 + dc), make_float2(accAV[f][2], accAV[f][3]));
        }
    }
}

extern "C" void kernel_launch(void* const* d_in, const int* in_sizes, int n_in,
                              void* d_out, int out_size) {
    const float* x    = (const float*)d_in[0];
    const int*   tags = (const int*)  d_in[1];
    const float* mk   = (const float*)d_in[2];
    const float* Wk_w = (const float*)d_in[3];
    const float* Wk_b = (const float*)d_in[4];
    const float* Wq_w = (const float*)d_in[5];
    const float* Wq_b = (const float*)d_in[6];
    const float* Wv_w = (const float*)d_in[7];
    const float* Wv_b = (const float*)d_in[8];

    float* ctx = (float*)d_out;                        // [8,16,128,64]
    float* p   = ctx + (size_t)BB*SS*TT*DD;            // [8,2048,2048]

    cudaFuncSetAttribute(qkv_kernel,  cudaFuncAttributeMaxDynamicSharedMemorySize, SMEM_QKV);
    cudaFuncSetAttribute(attn_kernel, cudaFuncAttributeMaxDynamicSharedMemorySize, SMEM_AT);

    qkv_kernel<<<128, 512, SMEM_QKV>>>(x, Wq_w, Wq_b, Wk_w, Wk_b, Wv_w, Wv_b);
    attn_kernel<<<dim3(SS, BB), 512, SMEM_AT>>>(tags, mk, ctx, p);
}